// round 7
// baseline (speedup 1.0000x reference)
#include <cuda_runtime.h>
#include <math.h>

// Persistent 16-CTA training kernel. Weights live in SMEM, column-sliced
// across CTAs. Cross-CTA exchange via volatile L2 scratch + monotonic global
// barrier. Lazy-rescale normalization: stored matrix m is the true
// post-update weight (unit-ish norm forever); scalar q = 1/max(||m||,EPS)
// applied on MV results and folded into the next rank-1 rewrite.
// Exactly equivalent to the reference algebra, with no unbounded growth.

#define NC 16
#define T  512
#define Dd 1024
#define Hh 256
#define Oo 64
#define NSTEPS 1024
#define LRc 0.01f
#define EPSc 1e-8f
#define C1 16   // H / NC
#define C3 4    // O / NC
#define BARS_PER_STEP 6
#define ARRIVALS_PER_LAUNCH ((unsigned long long)(NSTEPS * BARS_PER_STEP) * NC)
#define TOTAL_OUT (Dd * Hh + Hh * Hh + Hh * Oo)   // 344064

#define SMEM_FLOATS (16384 + 4096 + 1024 + 1024 + 256 + 256 + 256 + 256 + 64 + 256 + 256 + 64 + 32 + 4)
#define SMEM_BYTES (SMEM_FLOATS * 4)

__device__ volatile float g_a1[Hh];
__device__ volatile float g_a2[Hh];
__device__ volatile float g_a3[Oo];
__device__ volatile float g_o2part[NC * Hh];
__device__ volatile float g_o1part[NC * Hh];
__device__ volatile float g_ss[NC * 3];
__device__ unsigned long long g_epoch = 0ULL;
__device__ unsigned long long g_count = 0ULL;

__device__ __forceinline__ void gbar(unsigned long long target) {
    __syncthreads();
    if (threadIdx.x == 0) {
        __threadfence();
        atomicAdd(&g_count, 1ULL);
        volatile unsigned long long* p = &g_count;
        while (*p < target) { }
        __threadfence();
    }
    __syncthreads();
}

// Deterministic block-wide sum; result returned to all threads.
__device__ __forceinline__ float block_reduce(float v, float* sred) {
    #pragma unroll
    for (int o = 16; o; o >>= 1) v += __shfl_xor_sync(0xffffffffu, v, o);
    int w = threadIdx.x >> 5;
    if ((threadIdx.x & 31) == 0) sred[w] = v;
    __syncthreads();
    if (threadIdx.x < 32) {
        float t = (threadIdx.x < (T / 32)) ? sred[threadIdx.x] : 0.f;
        #pragma unroll
        for (int o = 8; o; o >>= 1) t += __shfl_xor_sync(0xffffffffu, t, o);
        if (threadIdx.x == 0) sred[16] = t;
    }
    __syncthreads();
    float r = sred[16];
    __syncthreads();
    return r;
}

__device__ __forceinline__ float sigmoidf(float p) {
    return 1.f / (1.f + expf(-p));
}

__device__ __forceinline__ float sanitize(float v) {
    return isfinite(v) ? v : 0.f;
}

__global__ void __launch_bounds__(T, 1) train_kernel(
    const float* __restrict__ X,     // [N, D]
    const float* __restrict__ Tg,    // [N, O]
    const float* __restrict__ W1g, const float* __restrict__ b1g,
    const float* __restrict__ W2g, const float* __restrict__ b2g,
    const float* __restrict__ W3g, const float* __restrict__ b3g,
    float* __restrict__ out, int out_size)
{
    extern __shared__ float sm[];
    float* sW1 = sm;                    // [C1][Dd] column-major slice (m1)
    float* sW2 = sW1 + C1 * Dd;         // [C1][Hh] (m2)
    float* sW3 = sW2 + C1 * Hh;         // [C3][Hh] (m3)
    float* sx  = sW3 + C3 * Hh;         // [Dd]
    float* sa1 = sx + Dd;               // [Hh]
    float* sa2 = sa1 + Hh;              // [Hh]
    float* so1 = sa2 + Hh;              // [Hh]
    float* so2 = so1 + Hh;              // [Hh]
    float* sd3 = so2 + Hh;              // [Oo]
    float* sb1 = sd3 + Oo;              // [Hh]
    float* sb2 = sb1 + Hh;              // [Hh]
    float* sb3 = sb2 + Hh;              // [Oo]
    float* sred = sb3 + Oo;             // [32]
    float* sc = sred + 32;              // q1, q2, q3

    __shared__ unsigned long long s_base;

    const int tid = threadIdx.x;
    const int cta = blockIdx.x;
    const int w = tid >> 5, lane = tid & 31;

    if (tid == 0) {
        unsigned long long e = atomicAdd(&g_epoch, 1ULL);
        s_base = (e / NC) * ARRIVALS_PER_LAUNCH;
        sc[0] = 1.f; sc[1] = 1.f; sc[2] = 1.f;  // step 0 uses raw weights
    }

    // ---- load weight slices ----
    for (int idx = tid; idx < C1 * Dd; idx += T) {
        int lc = idx & (C1 - 1), r = idx >> 4;
        sW1[lc * Dd + r] = W1g[r * Hh + cta * C1 + lc];
    }
    for (int idx = tid; idx < C1 * Hh; idx += T) {
        int lc = idx & (C1 - 1), i = idx >> 4;
        sW2[lc * Hh + i] = W2g[i * Hh + cta * C1 + lc];
    }
    for (int idx = tid; idx < C3 * Hh; idx += T) {
        int lc = idx & (C3 - 1), i = idx >> 2;
        sW3[lc * Hh + i] = W3g[i * Oo + cta * C3 + lc];
    }
    for (int i = tid; i < Hh; i += T) { sb1[i] = b1g[i]; sb2[i] = b2g[i]; }
    if (tid < Oo) sb3[tid] = b3g[tid];
    __syncthreads();

    unsigned long long bar = s_base;

    for (int step = 0; step < NSTEPS; ++step) {
        if (step > 0) {
            // q = 1 / max(||m||, EPS); m is the true post-update weight
            if (tid < 3) {
                float s = 0.f;
                #pragma unroll
                for (int c = 0; c < NC; c++) s += g_ss[c * 3 + tid];
                sc[tid] = 1.f / fmaxf(sqrtf(s), EPSc);
            }
            __syncthreads();
        }
        float q1 = sc[0], q2 = sc[1], q3 = sc[2];

        // ================= Phase A: fwd layer 1 =================
        const float* xp = X + step * Dd;
        for (int i = tid; i < Dd; i += T) sx[i] = xp[i];
        __syncthreads();
        {
            const float4* col4 = (const float4*)(sW1 + w * Dd);
            const float4* x4 = (const float4*)sx;
            float acc = 0.f;
            #pragma unroll
            for (int j = 0; j < Dd / 128; j++) {
                float4 a = col4[lane + 32 * j];
                float4 b = x4[lane + 32 * j];
                acc += a.x * b.x + a.y * b.y + a.z * b.z + a.w * b.w;
            }
            #pragma unroll
            for (int o = 16; o; o >>= 1) acc += __shfl_xor_sync(0xffffffffu, acc, o);
            if (lane == 0) {
                int g = cta * C1 + w;
                float pre = q1 * acc + sb1[g];
                g_a1[g] = sigmoidf(pre);
            }
        }
        bar += NC; gbar(bar);

        // ================= Phase B: fwd layer 2 =================
        for (int i = tid; i < Hh; i += T) sa1[i] = g_a1[i];
        __syncthreads();
        {
            const float4* col4 = (const float4*)(sW2 + w * Hh);
            const float4* a4 = (const float4*)sa1;
            float acc = 0.f;
            #pragma unroll
            for (int j = 0; j < Hh / 128; j++) {
                float4 a = col4[lane + 32 * j];
                float4 b = a4[lane + 32 * j];
                acc += a.x * b.x + a.y * b.y + a.z * b.z + a.w * b.w;
            }
            #pragma unroll
            for (int o = 16; o; o >>= 1) acc += __shfl_xor_sync(0xffffffffu, acc, o);
            if (lane == 0) {
                int g = cta * C1 + w;
                float pre = q2 * acc + sb2[g];
                g_a2[g] = sigmoidf(pre);
            }
        }
        bar += NC; gbar(bar);

        // ================= Phase C: fwd layer 3 =================
        for (int i = tid; i < Hh; i += T) sa2[i] = g_a2[i];
        __syncthreads();
        if (w < C3) {
            const float4* col4 = (const float4*)(sW3 + w * Hh);
            const float4* a4 = (const float4*)sa2;
            float acc = 0.f;
            #pragma unroll
            for (int j = 0; j < Hh / 128; j++) {
                float4 a = col4[lane + 32 * j];
                float4 b = a4[lane + 32 * j];
                acc += a.x * b.x + a.y * b.y + a.z * b.z + a.w * b.w;
            }
            #pragma unroll
            for (int o = 16; o; o >>= 1) acc += __shfl_xor_sync(0xffffffffu, acc, o);
            if (lane == 0) {
                int g = cta * C3 + w;
                float pre = q3 * acc + sb3[g];
                g_a3[g] = sigmoidf(pre);
            }
        }
        bar += NC; gbar(bar);

        // ===== Phase D: softmax, d3, o2 partials, W3 + b3 update =====
        if (w == 0) {
            float a3_0 = g_a3[lane];
            float a3_1 = g_a3[lane + 32];
            float t0 = Tg[step * Oo + lane];
            float t1 = Tg[step * Oo + lane + 32];
            float m = fmaxf(-a3_0, -a3_1);
            #pragma unroll
            for (int o = 16; o; o >>= 1) m = fmaxf(m, __shfl_xor_sync(0xffffffffu, m, o));
            float e0 = expf(-a3_0 - m), e1 = expf(-a3_1 - m);
            float s = e0 + e1;
            #pragma unroll
            for (int o = 16; o; o >>= 1) s += __shfl_xor_sync(0xffffffffu, s, o);
            float inv = 1.f / s;
            sd3[lane]      = (t0 - e0 * inv) * a3_0 * (1.f - a3_0);
            sd3[lane + 32] = (t1 - e1 * inv) * a3_1 * (1.f - a3_1);
        }
        __syncthreads();
        if (tid < Hh) {  // o2 partial from PRE-update m3 slice
            float p = 0.f;
            #pragma unroll
            for (int lc = 0; lc < C3; lc++) p += sW3[lc * Hh + tid] * sd3[cta * C3 + lc];
            g_o2part[cta * Hh + tid] = p;
        }
        __syncthreads();
        {
            float ss = 0.f;
            #pragma unroll
            for (int k = 0; k < (C3 * Hh) / T; k++) {
                int e = tid + k * T;
                int lc = e >> 8, i = e & 255;
                // m_new = q3*m - LR*a2*d3   (true post-update weight)
                float v = q3 * sW3[e] - LRc * sa2[i] * sd3[cta * C3 + lc];
                sW3[e] = v; ss += v * v;
            }
            float tot = block_reduce(ss, sred);
            if (tid == 0) g_ss[cta * 3 + 2] = tot;
        }
        {
            float bv = 0.f, sq = 0.f;
            if (tid < Oo) { bv = sb3[tid] - LRc * sd3[tid]; sq = bv * bv; }
            float bn = block_reduce(sq, sred);
            if (tid < Oo) sb3[tid] = bv / fmaxf(sqrtf(bn), EPSc);
        }
        bar += NC; gbar(bar);

        // ===== Phase E: o2 reduce, o1 partials, W2 + b2 update =====
        if (tid < Hh) {
            float s = 0.f;
            #pragma unroll
            for (int c = 0; c < NC; c++) s += g_o2part[c * Hh + tid];
            float a = sa2[tid];
            so2[tid] = q3 * s * a * (1.f - a);   // W3 = q3*m3 (pre-update)
        }
        __syncthreads();
        if (tid < Hh) {  // o1 partial from PRE-update m2 slice
            float p = 0.f;
            #pragma unroll
            for (int lc = 0; lc < C1; lc++) p += sW2[lc * Hh + tid] * so2[cta * C1 + lc];
            g_o1part[cta * Hh + tid] = p;
        }
        __syncthreads();
        {
            float ss = 0.f;
            #pragma unroll
            for (int k = 0; k < (C1 * Hh) / T; k++) {
                int e = tid + k * T;
                int lc = e >> 8, i = e & 255;
                float v = q2 * sW2[e] - LRc * sa1[i] * so2[cta * C1 + lc];
                sW2[e] = v; ss += v * v;
            }
            float tot = block_reduce(ss, sred);
            if (tid == 0) g_ss[cta * 3 + 1] = tot;
        }
        {
            float bv = 0.f, sq = 0.f;
            if (tid < Hh) { bv = sb2[tid] - LRc * so2[tid]; sq = bv * bv; }
            float bn = block_reduce(sq, sred);
            if (tid < Hh) sb2[tid] = bv / fmaxf(sqrtf(bn), EPSc);
        }
        bar += NC; gbar(bar);

        // ===== Phase F: o1 reduce, W1 + b1 update =====
        if (tid < Hh) {
            float s = 0.f;
            #pragma unroll
            for (int c = 0; c < NC; c++) s += g_o1part[c * Hh + tid];
            float a = sa1[tid];
            so1[tid] = q2 * s * a * (1.f - a);   // W2 = q2*m2 (pre-update)
        }
        __syncthreads();
        {
            float ss = 0.f;
            float4* W14 = (float4*)sW1;
            const float4* x4 = (const float4*)sx;
            #pragma unroll
            for (int k = 0; k < (C1 * Dd) / (4 * T); k++) {  // 8 iters
                int e4 = tid + k * T;
                int lc = e4 >> 8;
                int r4 = e4 & 255;
                float sv = LRc * so1[cta * C1 + lc];
                float4 wv = W14[e4];
                float4 xv = x4[r4];
                wv.x = q1 * wv.x - sv * xv.x;
                wv.y = q1 * wv.y - sv * xv.y;
                wv.z = q1 * wv.z - sv * xv.z;
                wv.w = q1 * wv.w - sv * xv.w;
                W14[e4] = wv;
                ss += wv.x * wv.x + wv.y * wv.y + wv.z * wv.z + wv.w * wv.w;
            }
            float tot = block_reduce(ss, sred);
            if (tid == 0) g_ss[cta * 3 + 0] = tot;
        }
        {
            float bv = 0.f, sq = 0.f;
            if (tid < Hh) { bv = sb1[tid] - LRc * so1[tid]; sq = bv * bv; }
            float bn = block_reduce(sq, sred);
            if (tid < Hh) sb1[tid] = bv / fmaxf(sqrtf(bn), EPSc);
        }
        bar += NC; gbar(bar);
    }

    // final scales from last step's norms
    if (tid < 3) {
        float s = 0.f;
        #pragma unroll
        for (int c = 0; c < NC; c++) s += g_ss[c * 3 + tid];
        sc[tid] = 1.f / fmaxf(sqrtf(s), EPSc);
    }
    __syncthreads();
    float q1 = sc[0], q2 = sc[1], q3 = sc[2];

    // write out: W1 | W2 | W3 (row-major), bounds-guarded, finite-sanitized
    for (int idx = tid; idx < C1 * Dd; idx += T) {
        int lc = idx & (C1 - 1), r = idx >> 4;
        int o = r * Hh + cta * C1 + lc;
        if (o < out_size) out[o] = sanitize(q1 * sW1[lc * Dd + r]);
    }
    for (int idx = tid; idx < C1 * Hh; idx += T) {
        int lc = idx & (C1 - 1), i = idx >> 4;
        int o = Dd * Hh + i * Hh + cta * C1 + lc;
        if (o < out_size) out[o] = sanitize(q2 * sW2[lc * Hh + i]);
    }
    for (int idx = tid; idx < C3 * Hh; idx += T) {
        int lc = idx & (C3 - 1), i = idx >> 2;
        int o = Dd * Hh + Hh * Hh + i * Oo + cta * C3 + lc;
        if (o < out_size) out[o] = sanitize(q3 * sW3[lc * Hh + i]);
    }
    // zero any tail beyond our payload (poison removal)
    for (int o = TOTAL_OUT + cta * T + tid; o < out_size; o += NC * T) out[o] = 0.f;
}

extern "C" void kernel_launch(void* const* d_in, const int* in_sizes, int n_in,
                              void* d_out, int out_size) {
    // Identify inputs by element count — robust to harness input ordering.
    // Collisions (targets vs W2 @65536, b1 vs b2 @256) resolve first-wins,
    // correct under both dict-insertion and alphabetical order.
    const float* X = 0; const float* Tg = 0;
    const float* W1 = 0; const float* b1 = 0;
    const float* W2 = 0; const float* b2 = 0;
    const float* W3 = 0; const float* b3 = 0;
    for (int i = 0; i < n_in; i++) {
        const float* p = (const float*)d_in[i];
        switch (in_sizes[i]) {
            case 1024 * 1024: X = p; break;                        // training_data
            case 1024 * 256:  W1 = p; break;                       // weights1
            case 256 * 256:   if (!Tg) Tg = p; else W2 = p; break; // targets, weights2
            case 256 * 64:    W3 = p; break;                       // weights3
            case 256:         if (!b1) b1 = p; else b2 = p; break; // biases1, biases2
            case 64:          b3 = p; break;                       // biases3
            default: break;
        }
    }
    cudaFuncSetAttribute(train_kernel, cudaFuncAttributeMaxDynamicSharedMemorySize, SMEM_BYTES);
    train_kernel<<<NC, T, SMEM_BYTES>>>(X, Tg, W1, b1, W2, b2, W3, b3,
                                        (float*)d_out, out_size);
}

// round 8
// speedup vs baseline: 1.6644x; 1.6644x over previous
#include <cuda_runtime.h>
#include <math.h>
#include <cstdint>

// One 8-CTA cluster, persistent. Weights column-sliced into SMEM per CTA.
// All cross-CTA exchange via DSMEM pushes (mapa + st.shared::cluster) made
// visible by barrier.cluster (release/acquire). Lazy-rescale normalization
// for W1/W2/W3 and b1 (store unnormalized m, scalar q = 1/max(||m||,EPS));
// b2/b3 normalized immediately (replicated identically in every CTA).

#define NC 8
#define T  512
#define Dd 1024
#define Hh 256
#define Oo 64
#define NSTEPS 1024
#define LRc 0.01f
#define EPSc 1e-8f
#define C1 32   // H / NC
#define C3 8    // O / NC
#define TOTAL_OUT (Dd * Hh + Hh * Hh + Hh * Oo)   // 344064

// ---- SMEM layout (floats) ----
#define OFF_W1    0            // [C1][Dd] col-major slice        32768
#define OFF_W2    32768        // [C1][Hh]                         8192
#define OFF_W3    40960        // [C3][Hh]                         2048
#define OFF_X     43008        // [Dd]                             1024
#define OFF_A1    44032        // [Hh]   full a1 (pushed)           256
#define OFF_A2    44288        // [Hh]   full a2 (pushed)           256
#define OFF_A3    44544        // [Oo]   full a3 (pushed)            64
#define OFF_D3    44608        // [Oo]                               64
#define OFF_O2ALL 44672        // [NC][Hh] o2 partials (pushed)    2048
#define OFF_O1ALL 46720        // [NC][C1] o1 partials (pushed)     256
#define OFF_SO2   46976        // [Hh]                              256
#define OFF_SCAL  47232        // [NC][4] norm partials (pushed)     32
#define OFF_STAGE 47264        // [C1] staging                       32
#define OFF_SO1   47296        // [C1]                               32
#define OFF_MB1   47328        // [C1] unnormalized b1 slice         32
#define OFF_B2    47360        // [Hh]                              256
#define OFF_B3    47616        // [Oo]                               64
#define OFF_SRED  47680        // [32]                               32
#define OFF_SQ    47712        // q1,q2,q3,qb1                        4
#define OFF_SCST  47716        // ss1,ss2,ss3,bn1 local partials      4
#define SMEM_FLOATS 47720
#define SMEM_BYTES (SMEM_FLOATS * 4)

__device__ __forceinline__ uint32_t smem_u32(const void* p) {
    uint32_t a;
    asm("{ .reg .u64 t; cvta.to.shared.u64 t, %1; cvt.u32.u64 %0, t; }"
        : "=r"(a) : "l"(p));
    return a;
}

__device__ __forceinline__ void st_peer(uint32_t laddr, uint32_t rank, float v) {
    uint32_t r;
    asm volatile("mapa.shared::cluster.u32 %0, %1, %2;" : "=r"(r) : "r"(laddr), "r"(rank));
    asm volatile("st.shared::cluster.f32 [%0], %1;" :: "r"(r), "f"(v) : "memory");
}

#define CLUSTER_SYNC() do { \
    asm volatile("barrier.cluster.arrive.aligned;" ::: "memory"); \
    asm volatile("barrier.cluster.wait.aligned;" ::: "memory");   \
} while (0)

// Deterministic block-wide sum; result returned to all threads.
__device__ __forceinline__ float block_reduce(float v, float* sred) {
    #pragma unroll
    for (int o = 16; o; o >>= 1) v += __shfl_xor_sync(0xffffffffu, v, o);
    int w = threadIdx.x >> 5;
    if ((threadIdx.x & 31) == 0) sred[w] = v;
    __syncthreads();
    if (threadIdx.x < 32) {
        float t = (threadIdx.x < (T / 32)) ? sred[threadIdx.x] : 0.f;
        #pragma unroll
        for (int o = 8; o; o >>= 1) t += __shfl_xor_sync(0xffffffffu, t, o);
        if (threadIdx.x == 0) sred[16] = t;
    }
    __syncthreads();
    float r = sred[16];
    __syncthreads();
    return r;
}

__device__ __forceinline__ float sigmoidf(float p) { return 1.f / (1.f + expf(-p)); }
__device__ __forceinline__ float sanitize(float v) { return isfinite(v) ? v : 0.f; }

__global__ void __launch_bounds__(T, 1) __cluster_dims__(NC, 1, 1)
train_kernel(const float* __restrict__ X, const float* __restrict__ Tg,
             const float* __restrict__ W1g, const float* __restrict__ b1g,
             const float* __restrict__ W2g, const float* __restrict__ b2g,
             const float* __restrict__ W3g, const float* __restrict__ b3g,
             float* __restrict__ out, int out_size)
{
    extern __shared__ float sm[];
    float* sW1   = sm + OFF_W1;
    float* sW2   = sm + OFF_W2;
    float* sW3   = sm + OFF_W3;
    float* sx    = sm + OFF_X;
    float* a1buf = sm + OFF_A1;
    float* a2buf = sm + OFF_A2;
    float* a3buf = sm + OFF_A3;
    float* d3    = sm + OFF_D3;
    float* o2all = sm + OFF_O2ALL;
    float* o1all = sm + OFF_O1ALL;
    float* so2   = sm + OFF_SO2;
    float* scal  = sm + OFF_SCAL;
    float* stage = sm + OFF_STAGE;
    float* so1   = sm + OFF_SO1;
    float* mb1   = sm + OFF_MB1;
    float* b2    = sm + OFF_B2;
    float* b3    = sm + OFF_B3;
    float* sred  = sm + OFF_SRED;
    float* sq    = sm + OFF_SQ;
    float* scst  = sm + OFF_SCST;

    const int tid = threadIdx.x;
    const int w = tid >> 5, lane = tid & 31;

    uint32_t me;
    asm("mov.u32 %0, %%cluster_ctarank;" : "=r"(me));
    const uint32_t sbase = smem_u32(sm);
    const uint32_t A1A = sbase + OFF_A1 * 4;
    const uint32_t A2A = sbase + OFF_A2 * 4;
    const uint32_t A3A = sbase + OFF_A3 * 4;
    const uint32_t O2A = sbase + OFF_O2ALL * 4;
    const uint32_t O1A = sbase + OFF_O1ALL * 4;
    const uint32_t SCA = sbase + OFF_SCAL * 4;

    // ---- init: load weight slices + biases ----
    for (int idx = tid; idx < C1 * Dd; idx += T) {
        int lc = idx & 31, r = idx >> 5;
        sW1[lc * Dd + r] = W1g[r * Hh + me * C1 + lc];
    }
    for (int idx = tid; idx < C1 * Hh; idx += T) {
        int lc = idx & 31, i = idx >> 5;
        sW2[lc * Hh + i] = W2g[i * Hh + me * C1 + lc];
    }
    for (int idx = tid; idx < C3 * Hh; idx += T) {
        int lc = idx & 7, i = idx >> 3;
        sW3[lc * Hh + i] = W3g[i * Oo + me * C3 + lc];
    }
    if (tid < C1) mb1[tid] = b1g[me * C1 + tid];
    if (tid < Hh) b2[tid] = b2g[tid];
    if (tid < Oo) b3[tid] = b3g[tid];
    if (tid < 4) sq[tid] = 1.f;    // step 0: raw weights/biases
    __syncthreads();

    for (int step = 0; step < NSTEPS; ++step) {
        if (step > 0) {
            if (tid < 4) {
                float s = 0.f;
                #pragma unroll
                for (int p = 0; p < NC; p++) s += scal[p * 4 + tid];
                sq[tid] = 1.f / fmaxf(sqrtf(s), EPSc);
            }
            __syncthreads();
        }
        const float q1 = sq[0], q2 = sq[1], q3 = sq[2], qb1 = sq[3];

        // ======== Phase A: fwd layer 1 (2 cols per warp) ========
        const float* xp = X + step * Dd;
        for (int i = tid; i < Dd; i += T) sx[i] = xp[i];
        __syncthreads();
        {
            const float4* x4 = (const float4*)sx;
            const float4* c0 = (const float4*)(sW1 + w * Dd);
            const float4* c1 = (const float4*)(sW1 + (w + 16) * Dd);
            float a0 = 0.f, a1v = 0.f;
            #pragma unroll
            for (int k = 0; k < 8; k++) {
                float4 xv = x4[lane + 32 * k];
                float4 u = c0[lane + 32 * k];
                float4 v = c1[lane + 32 * k];
                a0  += u.x * xv.x + u.y * xv.y + u.z * xv.z + u.w * xv.w;
                a1v += v.x * xv.x + v.y * xv.y + v.z * xv.z + v.w * xv.w;
            }
            #pragma unroll
            for (int o = 16; o; o >>= 1) {
                a0  += __shfl_xor_sync(0xffffffffu, a0, o);
                a1v += __shfl_xor_sync(0xffffffffu, a1v, o);
            }
            if (lane == 0) {
                stage[w]      = sigmoidf(q1 * a0  + qb1 * mb1[w]);
                stage[w + 16] = sigmoidf(q1 * a1v + qb1 * mb1[w + 16]);
            }
        }
        __syncthreads();
        if (tid < 256) {   // push a1 slice (32 vals) to all 8 CTAs
            int j = tid >> 3, p = tid & 7;
            st_peer(A1A + ((me * C1 + j) << 2), p, stage[j]);
        }
        CLUSTER_SYNC();

        // ======== Phase B: fwd layer 2 ========
        {
            const float4* a4 = (const float4*)a1buf;
            const float4* c0 = (const float4*)(sW2 + w * Hh);
            const float4* c1 = (const float4*)(sW2 + (w + 16) * Hh);
            float a0 = 0.f, a1v = 0.f;
            #pragma unroll
            for (int k = 0; k < 2; k++) {
                float4 xv = a4[lane + 32 * k];
                float4 u = c0[lane + 32 * k];
                float4 v = c1[lane + 32 * k];
                a0  += u.x * xv.x + u.y * xv.y + u.z * xv.z + u.w * xv.w;
                a1v += v.x * xv.x + v.y * xv.y + v.z * xv.z + v.w * xv.w;
            }
            #pragma unroll
            for (int o = 16; o; o >>= 1) {
                a0  += __shfl_xor_sync(0xffffffffu, a0, o);
                a1v += __shfl_xor_sync(0xffffffffu, a1v, o);
            }
            if (lane == 0) {
                stage[w]      = sigmoidf(q2 * a0  + b2[me * C1 + w]);
                stage[w + 16] = sigmoidf(q2 * a1v + b2[me * C1 + w + 16]);
            }
        }
        __syncthreads();
        if (tid < 256) {
            int j = tid >> 3, p = tid & 7;
            st_peer(A2A + ((me * C1 + j) << 2), p, stage[j]);
        }
        CLUSTER_SYNC();

        // ======== Phase C: fwd layer 3 (warps 0-7, 1 col each) ========
        if (w < C3) {
            const float4* a4 = (const float4*)a2buf;
            const float4* c0 = (const float4*)(sW3 + w * Hh);
            float a0 = 0.f;
            #pragma unroll
            for (int k = 0; k < 2; k++) {
                float4 xv = a4[lane + 32 * k];
                float4 u = c0[lane + 32 * k];
                a0 += u.x * xv.x + u.y * xv.y + u.z * xv.z + u.w * xv.w;
            }
            #pragma unroll
            for (int o = 16; o; o >>= 1) a0 += __shfl_xor_sync(0xffffffffu, a0, o);
            if (lane == 0) stage[w] = sigmoidf(q3 * a0 + b3[me * C3 + w]);
        }
        __syncthreads();
        if (tid < 64) {    // push a3 slice (8 vals) to all 8 CTAs
            int j = tid >> 3, p = tid & 7;
            st_peer(A3A + ((me * C3 + j) << 2), p, stage[j]);
        }
        CLUSTER_SYNC();

        // ======== Phase D: softmax+d3, o2 partials, W3+b3 update ========
        if (w == 0) {
            float a3_0 = a3buf[lane], a3_1 = a3buf[lane + 32];
            float t0 = Tg[step * Oo + lane], t1 = Tg[step * Oo + lane + 32];
            float m = fmaxf(-a3_0, -a3_1);
            #pragma unroll
            for (int o = 16; o; o >>= 1) m = fmaxf(m, __shfl_xor_sync(0xffffffffu, m, o));
            float e0 = expf(-a3_0 - m), e1 = expf(-a3_1 - m);
            float s = e0 + e1;
            #pragma unroll
            for (int o = 16; o; o >>= 1) s += __shfl_xor_sync(0xffffffffu, s, o);
            float inv = 1.f / s;
            d3[lane]      = (t0 - e0 * inv) * a3_0 * (1.f - a3_0);
            d3[lane + 32] = (t1 - e1 * inv) * a3_1 * (1.f - a3_1);
        }
        __syncthreads();
        if (tid < Hh) {    // o2 partial from PRE-update m3; push to all CTAs
            float v = 0.f;
            #pragma unroll
            for (int lc = 0; lc < C3; lc++) v += sW3[lc * Hh + tid] * d3[me * C3 + lc];
            uint32_t slot = O2A + ((me * Hh + tid) << 2);
            #pragma unroll
            for (int p = 0; p < NC; p++) st_peer(slot, p, v);
        }
        __syncthreads();
        {
            float ss = 0.f;
            #pragma unroll
            for (int k = 0; k < (C3 * Hh) / T; k++) {   // 4 iters
                int e = tid + k * T;
                int lc = e >> 8, i = e & 255;
                float v = q3 * sW3[e] - LRc * a2buf[i] * d3[me * C3 + lc];
                sW3[e] = v; ss += v * v;
            }
            float tot = block_reduce(ss, sred);
            if (tid == 0) scst[2] = tot;
        }
        {
            float bv = 0.f, sqv = 0.f;
            if (tid < Oo) { bv = b3[tid] - LRc * d3[tid]; sqv = bv * bv; }
            float bn = block_reduce(sqv, sred);
            if (tid < Oo) b3[tid] = bv / fmaxf(sqrtf(bn), EPSc);
        }
        CLUSTER_SYNC();

        // ======== Phase E: o2 reduce, o1 partials, W2+b2 update ========
        if (tid < Hh) {
            float s = 0.f;
            #pragma unroll
            for (int p = 0; p < NC; p++) s += o2all[p * Hh + tid];
            float a = a2buf[tid];
            so2[tid] = q3 * s * a * (1.f - a);
        }
        __syncthreads();
        {
            float bv = 0.f, sqv = 0.f;
            if (tid < Hh) { bv = b2[tid] - LRc * so2[tid]; sqv = bv * bv; }
            float bn = block_reduce(sqv, sred);
            if (tid < Hh) b2[tid] = bv / fmaxf(sqrtf(bn), EPSc);
        }
        if (tid < Hh) {    // o1 partial from PRE-update m2; push to owner only
            float v = 0.f;
            #pragma unroll
            for (int lc = 0; lc < C1; lc++) v += sW2[lc * Hh + tid] * so2[me * C1 + lc];
            st_peer(O1A + ((me * C1 + (tid & 31)) << 2), tid >> 5, v);
        }
        __syncthreads();
        {
            float ss = 0.f;
            #pragma unroll
            for (int k = 0; k < (C1 * Hh) / T; k++) {   // 16 iters
                int e = tid + k * T;
                int lc = e >> 8, i = e & 255;
                float v = q2 * sW2[e] - LRc * a1buf[i] * so2[me * C1 + lc];
                sW2[e] = v; ss += v * v;
            }
            float tot = block_reduce(ss, sred);
            if (tid == 0) scst[1] = tot;
        }
        CLUSTER_SYNC();

        // ======== Phase F: o1 reduce, W1+b1 update, scalar push ========
        float bn1c = 0.f;
        if (tid < C1) {
            float s = 0.f;
            #pragma unroll
            for (int p = 0; p < NC; p++) s += o1all[p * C1 + tid];
            float a = a1buf[me * C1 + tid];
            float ov = q2 * s * a * (1.f - a);
            so1[tid] = ov;
            float nb = qb1 * mb1[tid] - LRc * ov;
            mb1[tid] = nb;
            bn1c = nb * nb;
        }
        {
            float bn1 = block_reduce(bn1c, sred);   // also orders so1 writes
            if (tid == 0) scst[3] = bn1;
        }
        {
            float ss = 0.f;
            float4* W14 = (float4*)sW1;
            const float4* x4 = (const float4*)sx;
            #pragma unroll
            for (int k = 0; k < (C1 * Dd) / (4 * T); k++) {   // 16 iters
                int e4 = tid + k * T;
                int lc = e4 >> 8, r4 = e4 & 255;
                float sv = LRc * so1[lc];
                float4 wv = W14[e4];
                float4 xv = x4[r4];
                wv.x = q1 * wv.x - sv * xv.x;
                wv.y = q1 * wv.y - sv * xv.y;
                wv.z = q1 * wv.z - sv * xv.z;
                wv.w = q1 * wv.w - sv * xv.w;
                W14[e4] = wv;
                ss += wv.x * wv.x + wv.y * wv.y + wv.z * wv.z + wv.w * wv.w;
            }
            float tot = block_reduce(ss, sred);
            if (tid == 0) scst[0] = tot;
        }
        __syncthreads();
        if (tid < 32) {    // push 4 norm partials to all 8 CTAs
            int k = tid >> 3, p = tid & 7;
            st_peer(SCA + ((me * 4 + k) << 2), p, scst[k]);
        }
        CLUSTER_SYNC();
    }

    // final scales
    if (tid < 3) {
        float s = 0.f;
        #pragma unroll
        for (int p = 0; p < NC; p++) s += scal[p * 4 + tid];
        sq[tid] = 1.f / fmaxf(sqrtf(s), EPSc);
    }
    __syncthreads();
    const float q1 = sq[0], q2 = sq[1], q3 = sq[2];

    // write out: W1 | W2 | W3 (row-major), bounds-guarded, sanitized
    for (int idx = tid; idx < C1 * Dd; idx += T) {
        int lc = idx & 31, r = idx >> 5;
        int o = r * Hh + me * C1 + lc;
        if (o < out_size) out[o] = sanitize(q1 * sW1[lc * Dd + r]);
    }
    for (int idx = tid; idx < C1 * Hh; idx += T) {
        int lc = idx & 31, i = idx >> 5;
        int o = Dd * Hh + i * Hh + me * C1 + lc;
        if (o < out_size) out[o] = sanitize(q2 * sW2[lc * Hh + i]);
    }
    for (int idx = tid; idx < C3 * Hh; idx += T) {
        int lc = idx & 7, i = idx >> 3;
        int o = Dd * Hh + Hh * Hh + i * Oo + me * C3 + lc;
        if (o < out_size) out[o] = sanitize(q3 * sW3[lc * Hh + i]);
    }
    for (int o = TOTAL_OUT + (int)me * T + tid; o < out_size; o += NC * T) out[o] = 0.f;
}

extern "C" void kernel_launch(void* const* d_in, const int* in_sizes, int n_in,
                              void* d_out, int out_size) {
    // Identify inputs by element count (robust to harness ordering).
    const float* X = 0; const float* Tg = 0;
    const float* W1 = 0; const float* b1 = 0;
    const float* W2 = 0; const float* b2 = 0;
    const float* W3 = 0; const float* b3 = 0;
    for (int i = 0; i < n_in; i++) {
        const float* p = (const float*)d_in[i];
        switch (in_sizes[i]) {
            case 1024 * 1024: X = p; break;
            case 1024 * 256:  W1 = p; break;
            case 256 * 256:   if (!Tg) Tg = p; else W2 = p; break;
            case 256 * 64:    W3 = p; break;
            case 256:         if (!b1) b1 = p; else b2 = p; break;
            case 64:          b3 = p; break;
            default: break;
        }
    }
    cudaFuncSetAttribute(train_kernel, cudaFuncAttributeMaxDynamicSharedMemorySize, SMEM_BYTES);
    train_kernel<<<NC, T, SMEM_BYTES>>>(X, Tg, W1, b1, W2, b2, W3, b3,
                                        (float*)d_out, out_size);
}

// round 9
// speedup vs baseline: 1.9317x; 1.1607x over previous
#include <cuda_runtime.h>
#include <math.h>
#include <cstdint>

// One 16-CTA (nonportable) cluster, persistent. W1/W2 column-sliced per CTA,
// W2 additionally row-sliced (backward), W3 fully replicated -> entire
// backward pass is CTA-local. 3 cluster syncs per step: a1, a2, norm scalars.
// Lazy-rescale normalization everywhere (store unnormalized m, scalar
// q = 1/max(||m||,EPS)); replicated quantities (W3, b2, b3) get locally
// computed, bit-identical scalars; sliced ones (W1, W2, b1) exchange 3
// partials per step.

#define NC 16
#define T  512
#define Dd 1024
#define Hh 256
#define Oo 64
#define NSTEPS 1024
#define LRc 0.01f
#define EPSc 1e-8f
#define C1 16                     // H / NC
#define TOTAL_OUT (Dd * Hh + Hh * Hh + Hh * Oo)   // 344064

// ---- SMEM layout (float offsets) ----
#define OFF_M1    0        // [C1][Dd]  W1 col slice            16384
#define OFF_M2C   16384    // [C1][Hh]  W2 col slice             4096
#define OFF_M2R   20480    // [C1][Hh]  W2 row slice             4096
#define OFF_M3    24576    // [Oo][Hh]  W3 full, [j][i]         16384
#define OFF_X     40960    // [2][Dd]   x double buffer          2048
#define OFF_TG    43008    // [2][Oo]   target double buffer      128
#define OFF_A1    43136    // [Hh]                                256
#define OFF_A2    43392    // [Hh]                                256
#define OFF_A3    43648    // [Oo]                                 64
#define OFF_D3    43712    // [Oo]                                 64
#define OFF_O2    43776    // [Hh]                                256
#define OFF_O1    44032    // [C1]                                 16
#define OFF_MB1   44048    // [C1]                                 16
#define OFF_MB2   44064    // [Hh]                                256
#define OFF_MB3   44320    // [Oo]                                 64
#define OFF_STAGE 44384    // [C1]                                 16
#define OFF_SRED  44400    // [16][6]                              96
#define OFF_SQ    44496    // q1,q2,q3,qb1,qb2,qb3                  8
#define OFF_SPART 44504    // [NC][3] pushed ss1,ss2,bn1           48
#define SMEM_FLOATS 44552
#define SMEM_BYTES (SMEM_FLOATS * 4)

__device__ __forceinline__ uint32_t smem_u32(const void* p) {
    uint32_t a;
    asm("{ .reg .u64 t; cvta.to.shared.u64 t, %1; cvt.u32.u64 %0, t; }"
        : "=r"(a) : "l"(p));
    return a;
}

__device__ __forceinline__ void st_peer(uint32_t laddr, uint32_t rank, float v) {
    uint32_t r;
    asm volatile("mapa.shared::cluster.u32 %0, %1, %2;" : "=r"(r) : "r"(laddr), "r"(rank));
    asm volatile("st.shared::cluster.f32 [%0], %1;" :: "r"(r), "f"(v) : "memory");
}

#define CLUSTER_SYNC() do { \
    asm volatile("barrier.cluster.arrive.aligned;" ::: "memory"); \
    asm volatile("barrier.cluster.wait.aligned;" ::: "memory");   \
} while (0)

__device__ __forceinline__ float sigmoidf(float p) { return 1.f / (1.f + expf(-p)); }
__device__ __forceinline__ float sanitize(float v) { return isfinite(v) ? v : 0.f; }
__device__ __forceinline__ float dot4(float4 a, float4 b) {
    return a.x * b.x + a.y * b.y + a.z * b.z + a.w * b.w;
}

__global__ void __launch_bounds__(T, 1)
train_kernel(const float* __restrict__ X, const float* __restrict__ Tg,
             const float* __restrict__ W1g, const float* __restrict__ b1g,
             const float* __restrict__ W2g, const float* __restrict__ b2g,
             const float* __restrict__ W3g, const float* __restrict__ b3g,
             float* __restrict__ out, int out_size)
{
    extern __shared__ float sm[];
    float* m1    = sm + OFF_M1;
    float* m2c   = sm + OFF_M2C;
    float* m2r   = sm + OFF_M2R;
    float* m3    = sm + OFF_M3;     // [j][i] layout
    float* xb    = sm + OFF_X;
    float* tgb   = sm + OFF_TG;
    float* a1buf = sm + OFF_A1;
    float* a2buf = sm + OFF_A2;
    float* a3buf = sm + OFF_A3;
    float* d3    = sm + OFF_D3;
    float* o2    = sm + OFF_O2;
    float* o1s   = sm + OFF_O1;
    float* mb1   = sm + OFF_MB1;
    float* mb2   = sm + OFF_MB2;
    float* mb3   = sm + OFF_MB3;
    float* stage = sm + OFF_STAGE;
    float* sred  = sm + OFF_SRED;
    float* sq    = sm + OFF_SQ;
    float* spart = sm + OFF_SPART;

    const int tid = threadIdx.x;
    const int w = tid >> 5, lane = tid & 31;

    uint32_t me;
    asm("mov.u32 %0, %%cluster_ctarank;" : "=r"(me));
    const uint32_t sbase = smem_u32(sm);
    const uint32_t A1A = sbase + OFF_A1 * 4;
    const uint32_t A2A = sbase + OFF_A2 * 4;
    const uint32_t SPA = sbase + OFF_SPART * 4;

    // ---- init ----
    for (int idx = tid; idx < C1 * Dd; idx += T) {      // W1 col slice
        int c = idx & 15, r = idx >> 4;
        m1[c * Dd + r] = W1g[r * Hh + me * C1 + c];
    }
    for (int idx = tid; idx < C1 * Hh; idx += T) {      // W2 col slice
        int c = idx & 15, i = idx >> 4;
        m2c[c * Hh + i] = W2g[i * Hh + me * C1 + c];
    }
    for (int idx = tid; idx < C1 * Hh; idx += T) {      // W2 row slice
        int r = idx >> 8, j = idx & 255;
        m2r[r * Hh + j] = W2g[(me * C1 + r) * Hh + j];
    }
    for (int idx = tid; idx < Oo * Hh; idx += T) {      // W3 full, [j][i]
        int j = idx >> 8, i = idx & 255;
        m3[idx] = W3g[i * Oo + j];
    }
    if (tid < C1) mb1[tid] = b1g[me * C1 + tid];
    if (tid < Hh) mb2[tid] = b2g[tid];
    if (tid < Oo) mb3[tid] = b3g[tid];
    if (tid < 6) sq[tid] = 1.f;
    // preload x0 and tg0
    if (tid < 256) ((float4*)xb)[tid] = ((const float4*)X)[tid];
    else if (tid < 320) tgb[tid - 256] = Tg[tid - 256];
    __syncthreads();

    for (int step = 0; step < NSTEPS; ++step) {
        const int par = step & 1;
        if (step > 0) {
            if (tid < 3) {
                float s = 0.f;
                #pragma unroll
                for (int p = 0; p < NC; p++) s += spart[p * 3 + tid];
                float qq = 1.f / fmaxf(sqrtf(s), EPSc);
                sq[tid == 0 ? 0 : (tid == 1 ? 1 : 3)] = qq;
            }
            __syncthreads();
        }
        const float q1 = sq[0], q2 = sq[1], q3 = sq[2];
        const float qb1 = sq[3], qb2 = sq[4], qb3 = sq[5];
        const float* xc = xb + par * Dd;
        const float4* x4 = (const float4*)xc;

        // ======== Phase A: fwd layer 1 (warp w -> col w) ========
        {
            const float4* c4 = (const float4*)(m1 + w * Dd);
            float acc = 0.f;
            #pragma unroll
            for (int k = 0; k < 8; k++)
                acc += dot4(c4[lane + 32 * k], x4[lane + 32 * k]);
            #pragma unroll
            for (int o = 16; o; o >>= 1) acc += __shfl_xor_sync(0xffffffffu, acc, o);
            if (lane == 0) stage[w] = sigmoidf(q1 * acc + qb1 * mb1[w]);
        }
        __syncthreads();
        if (tid < 256) {
            int j = tid >> 4, p = tid & 15;
            st_peer(A1A + ((me * C1 + j) << 2), p, stage[j]);
        }
        CLUSTER_SYNC();

        // ======== Phase B: fwd layer 2 ========
        {
            const float4* a14 = (const float4*)a1buf;
            const float4* c4 = (const float4*)(m2c + w * Hh);
            float acc = 0.f;
            #pragma unroll
            for (int k = 0; k < 2; k++)
                acc += dot4(c4[lane + 32 * k], a14[lane + 32 * k]);
            #pragma unroll
            for (int o = 16; o; o >>= 1) acc += __shfl_xor_sync(0xffffffffu, acc, o);
            if (lane == 0) stage[w] = sigmoidf(q2 * acc + qb2 * mb2[me * C1 + w]);
        }
        __syncthreads();
        if (tid < 256) {
            int j = tid >> 4, p = tid & 15;
            st_peer(A2A + ((me * C1 + j) << 2), p, stage[j]);
        }
        CLUSTER_SYNC();

        // ======== Local region (everything else) ========
        // prefetch next x and targets into the other buffers
        if (step + 1 < NSTEPS) {
            if (tid < 256)
                ((float4*)(xb + (par ^ 1) * Dd))[tid] =
                    ((const float4*)(X + (step + 1) * Dd))[tid];
            else if (tid < 320)
                tgb[(par ^ 1) * Oo + (tid - 256)] = Tg[(step + 1) * Oo + (tid - 256)];
        }

        // (i) a3 full: warp w handles j = w, w+16, w+32, w+48
        {
            const float4* a24 = (const float4*)a2buf;
            float acc[4] = {0.f, 0.f, 0.f, 0.f};
            #pragma unroll
            for (int s = 0; s < 4; s++) {
                const float4* r4 = (const float4*)(m3 + (w + 16 * s) * Hh);
                #pragma unroll
                for (int k = 0; k < 2; k++)
                    acc[s] += dot4(r4[lane + 32 * k], a24[lane + 32 * k]);
            }
            #pragma unroll
            for (int o = 16; o; o >>= 1) {
                #pragma unroll
                for (int s = 0; s < 4; s++)
                    acc[s] += __shfl_xor_sync(0xffffffffu, acc[s], o);
            }
            if (lane == 0) {
                #pragma unroll
                for (int s = 0; s < 4; s++) {
                    int j = w + 16 * s;
                    a3buf[j] = sigmoidf(q3 * acc[s] + qb3 * mb3[j]);
                }
            }
        }
        __syncthreads();

        // (ii) softmax + d3 (warp 0)
        if (w == 0) {
            const float* tgc = tgb + par * Oo;
            float a3_0 = a3buf[lane], a3_1 = a3buf[lane + 32];
            float t0 = tgc[lane], t1 = tgc[lane + 32];
            float m = fmaxf(-a3_0, -a3_1);
            #pragma unroll
            for (int o = 16; o; o >>= 1) m = fmaxf(m, __shfl_xor_sync(0xffffffffu, m, o));
            float e0 = expf(-a3_0 - m), e1 = expf(-a3_1 - m);
            float s = e0 + e1;
            #pragma unroll
            for (int o = 16; o; o >>= 1) s += __shfl_xor_sync(0xffffffffu, s, o);
            float inv = 1.f / s;
            d3[lane]      = (t0 - e0 * inv) * a3_0 * (1.f - a3_0);
            d3[lane + 32] = (t1 - e1 * inv) * a3_1 * (1.f - a3_1);
        }
        __syncthreads();

        // (iii) o2 full (pre-update m3), then o1 slice (pre-update m2r)
        if (tid < Hh) {
            int i = tid;
            float raw = 0.f;
            #pragma unroll 8
            for (int j = 0; j < Oo; j++) raw += m3[j * Hh + i] * d3[j];
            float a = a2buf[i];
            o2[i] = q3 * raw * a * (1.f - a);
        }
        __syncthreads();
        {
            const float4* o24 = (const float4*)o2;
            const float4* r4 = (const float4*)(m2r + w * Hh);
            float acc = 0.f;
            #pragma unroll
            for (int k = 0; k < 2; k++)
                acc += dot4(r4[lane + 32 * k], o24[lane + 32 * k]);
            #pragma unroll
            for (int o = 16; o; o >>= 1) acc += __shfl_xor_sync(0xffffffffu, acc, o);
            float a = a1buf[me * C1 + w];
            float ov = q2 * acc * a * (1.f - a);
            if (lane == 0) {
                o1s[w] = ov;
                mb1[w] = qb1 * mb1[w] - LRc * ov;     // b1 slice update
            }
        }
        __syncthreads();

        // (iv) all weight/bias updates + fused norm accumulation
        float ss1 = 0.f, ss2 = 0.f, ss3 = 0.f, bn1 = 0.f, bn2 = 0.f, bn3 = 0.f;
        {
            float4* m34 = (float4*)m3;
            const float4* a24 = (const float4*)a2buf;
            #pragma unroll
            for (int k = 0; k < 8; k++) {          // W3 full: 4096 float4
                int e4 = tid + 512 * k;
                int j = e4 >> 6, i4 = e4 & 63;
                float sv = LRc * d3[j];
                float4 wv = m34[e4], av = a24[i4];
                wv.x = q3 * wv.x - sv * av.x;
                wv.y = q3 * wv.y - sv * av.y;
                wv.z = q3 * wv.z - sv * av.z;
                wv.w = q3 * wv.w - sv * av.w;
                m34[e4] = wv;
                ss3 += dot4(wv, wv);
            }
        }
        {
            float4* mc4 = (float4*)m2c;
            const float4* a14 = (const float4*)a1buf;
            #pragma unroll
            for (int k = 0; k < 2; k++) {          // W2 col slice: 1024 float4
                int e4 = tid + 512 * k;
                int c = e4 >> 6, i4 = e4 & 63;
                float sv = LRc * o2[me * C1 + c];
                float4 wv = mc4[e4], av = a14[i4];
                wv.x = q2 * wv.x - sv * av.x;
                wv.y = q2 * wv.y - sv * av.y;
                wv.z = q2 * wv.z - sv * av.z;
                wv.w = q2 * wv.w - sv * av.w;
                mc4[e4] = wv;
                ss2 += dot4(wv, wv);
            }
        }
        {
            float4* mr4 = (float4*)m2r;
            const float4* o24 = (const float4*)o2;
            #pragma unroll
            for (int k = 0; k < 2; k++) {          // W2 row slice: 1024 float4
                int e4 = tid + 512 * k;
                int r = e4 >> 6, j4 = e4 & 63;
                float sv = LRc * a1buf[me * C1 + r];
                float4 wv = mr4[e4], ov = o24[j4];
                wv.x = q2 * wv.x - sv * ov.x;
                wv.y = q2 * wv.y - sv * ov.y;
                wv.z = q2 * wv.z - sv * ov.z;
                wv.w = q2 * wv.w - sv * ov.w;
                mr4[e4] = wv;
            }
        }
        {
            float4* m14 = (float4*)m1;
            #pragma unroll
            for (int k = 0; k < 8; k++) {          // W1 col slice: 4096 float4
                int e4 = tid + 512 * k;
                int c = e4 >> 8, r4 = e4 & 255;
                float sv = LRc * o1s[c];
                float4 wv = m14[e4], xv = x4[r4];
                wv.x = q1 * wv.x - sv * xv.x;
                wv.y = q1 * wv.y - sv * xv.y;
                wv.z = q1 * wv.z - sv * xv.z;
                wv.w = q1 * wv.w - sv * xv.w;
                m14[e4] = wv;
                ss1 += dot4(wv, wv);
            }
        }
        if (tid < Hh) {                            // b2 (replicated)
            float v = qb2 * mb2[tid] - LRc * o2[tid];
            mb2[tid] = v; bn2 = v * v;
        }
        if (tid < Oo) {                            // b3 (replicated)
            float v = qb3 * mb3[tid] - LRc * d3[tid];
            mb3[tid] = v; bn3 = v * v;
        }
        if (tid < C1) { float v = mb1[tid]; bn1 = v * v; }   // b1 (already updated)

        // fused 6-way block reduce
        {
            float vals[6] = {ss1, ss2, ss3, bn1, bn2, bn3};
            #pragma unroll
            for (int o = 16; o; o >>= 1) {
                #pragma unroll
                for (int s = 0; s < 6; s++)
                    vals[s] += __shfl_xor_sync(0xffffffffu, vals[s], o);
            }
            if (lane == 0) {
                #pragma unroll
                for (int s = 0; s < 6; s++) sred[w * 6 + s] = vals[s];
            }
        }
        __syncthreads();
        if (w < 6) {
            float v = (lane < 16) ? sred[lane * 6 + w] : 0.f;
            #pragma unroll
            for (int o = 16; o; o >>= 1) v += __shfl_xor_sync(0xffffffffu, v, o);
            // w: 0=ss1, 1=ss2, 2=ss3, 3=bn1, 4=bn2, 5=bn3
            if (w == 2) { if (lane == 0) sq[2] = 1.f / fmaxf(sqrtf(v), EPSc); }
            else if (w == 4) { if (lane == 0) sq[4] = 1.f / fmaxf(sqrtf(v), EPSc); }
            else if (w == 5) { if (lane == 0) sq[5] = 1.f / fmaxf(sqrtf(v), EPSc); }
            else {
                int slot = (w == 0) ? 0 : ((w == 1) ? 1 : 2);
                if (lane < 16) st_peer(SPA + ((me * 3 + slot) << 2), lane, v);
            }
        }
        CLUSTER_SYNC();
    }

    // final scales
    if (tid < 3) {
        float s = 0.f;
        #pragma unroll
        for (int p = 0; p < NC; p++) s += spart[p * 3 + tid];
        float qq = 1.f / fmaxf(sqrtf(s), EPSc);
        sq[tid == 0 ? 0 : (tid == 1 ? 1 : 3)] = qq;
    }
    __syncthreads();
    const float q1 = sq[0], q2 = sq[1], q3 = sq[2];

    // write out: W1 | W2 | W3 (row-major), bounds-guarded, sanitized
    for (int idx = tid; idx < C1 * Dd; idx += T) {
        int c = idx & 15, r = idx >> 4;
        int o = r * Hh + me * C1 + c;
        if (o < out_size) out[o] = sanitize(q1 * m1[c * Dd + r]);
    }
    for (int idx = tid; idx < C1 * Hh; idx += T) {
        int c = idx & 15, i = idx >> 4;
        int o = Dd * Hh + i * Hh + me * C1 + c;
        if (o < out_size) out[o] = sanitize(q2 * m2c[c * Hh + i]);
    }
    for (int idx = tid; idx < 4 * Hh; idx += T) {   // W3: 4 j-cols per CTA
        int j = me * 4 + (idx & 3), i = idx >> 2;
        int o = Dd * Hh + Hh * Hh + i * Oo + j;
        if (o < out_size) out[o] = sanitize(q3 * m3[j * Hh + i]);
    }
    for (int o = TOTAL_OUT + (int)me * T + tid; o < out_size; o += NC * T) out[o] = 0.f;
}

extern "C" void kernel_launch(void* const* d_in, const int* in_sizes, int n_in,
                              void* d_out, int out_size) {
    // Identify inputs by element count (robust to harness ordering).
    const float* X = 0; const float* Tg = 0;
    const float* W1 = 0; const float* b1 = 0;
    const float* W2 = 0; const float* b2 = 0;
    const float* W3 = 0; const float* b3 = 0;
    for (int i = 0; i < n_in; i++) {
        const float* p = (const float*)d_in[i];
        switch (in_sizes[i]) {
            case 1024 * 1024: X = p; break;
            case 1024 * 256:  W1 = p; break;
            case 256 * 256:   if (!Tg) Tg = p; else W2 = p; break;
            case 256 * 64:    W3 = p; break;
            case 256:         if (!b1) b1 = p; else b2 = p; break;
            case 64:          b3 = p; break;
            default: break;
        }
    }
    cudaFuncSetAttribute(train_kernel, cudaFuncAttributeMaxDynamicSharedMemorySize, SMEM_BYTES);
    cudaFuncSetAttribute(train_kernel, cudaFuncAttributeNonPortableClusterSizeAllowed, 1);

    cudaLaunchConfig_t cfg = {};
    cfg.gridDim = dim3(NC, 1, 1);
    cfg.blockDim = dim3(T, 1, 1);
    cfg.dynamicSmemBytes = SMEM_BYTES;
    cudaLaunchAttribute attrs[1];
    attrs[0].id = cudaLaunchAttributeClusterDimension;
    attrs[0].val.clusterDim.x = NC;
    attrs[0].val.clusterDim.y = 1;
    attrs[0].val.clusterDim.z = 1;
    cfg.attrs = attrs;
    cfg.numAttrs = 1;
    cudaLaunchKernelEx(&cfg, train_kernel, X, Tg, W1, b1, W2, b2, W3, b3,
                       (float*)d_out, out_size);
}